// round 5
// baseline (speedup 1.0000x reference)
#include <cuda_runtime.h>

#define B 256
#define S 2048
#define V 100000
#define E 128

// __device__ scratch (no cudaMalloc allowed).
__device__ float g_proj[V];          // proj[v] = dot(emb[v], fc_w)
__device__ float g_part[B * 4];      // 4 partial sums per batch row
__device__ unsigned int g_cnt[B];    // arrival tickets (reset to 0 by last arriver)

// Kernel 1 v3: warp handles 8 vocab rows; lane = (row-sub, quarter). All 8
// emb float4 loads are issued BEFORE any fc_w use so ptxas front-batches them
// (MLP=8/lane). fc_w chunks re-loaded per FMA group — 512B table, pure L1 hits.
// __launch_bounds__(256, 4) gives a 64-reg budget so all 8 loads stay live
// (previous build got squeezed to 33 regs -> MLP collapsed -> DRAM 54%).
__global__ void __launch_bounds__(256, 4) proj_kernel(const float* __restrict__ emb,
                                                      const float* __restrict__ fc_w) {
    const int lane = threadIdx.x & 31;
    const int warp = threadIdx.x >> 5;
    const int q    = lane & 3;
    const int sub  = lane >> 2;

    const int row  = blockIdx.x * 64 + warp * 8 + sub;
    const bool valid = (row < V);
    const int rowc = valid ? row : (V - 1);   // clamp: lanes stay converged for shfl

    const float4* rp = reinterpret_cast<const float4*>(emb) + (size_t)rowc * (E / 4);

    // --- 8 independent loads, front-batched ---
    float4 e0 = rp[q +  0];
    float4 e1 = rp[q +  4];
    float4 e2 = rp[q +  8];
    float4 e3 = rp[q + 12];
    float4 e4 = rp[q + 16];
    float4 e5 = rp[q + 20];
    float4 e6 = rp[q + 24];
    float4 e7 = rp[q + 28];

    const float4* wp = reinterpret_cast<const float4*>(fc_w);
    float acc = 0.0f;
    float4 w;
    w = wp[q +  0]; acc = fmaf(e0.x,w.x,acc); acc = fmaf(e0.y,w.y,acc); acc = fmaf(e0.z,w.z,acc); acc = fmaf(e0.w,w.w,acc);
    w = wp[q +  4]; acc = fmaf(e1.x,w.x,acc); acc = fmaf(e1.y,w.y,acc); acc = fmaf(e1.z,w.z,acc); acc = fmaf(e1.w,w.w,acc);
    w = wp[q +  8]; acc = fmaf(e2.x,w.x,acc); acc = fmaf(e2.y,w.y,acc); acc = fmaf(e2.z,w.z,acc); acc = fmaf(e2.w,w.w,acc);
    w = wp[q + 12]; acc = fmaf(e3.x,w.x,acc); acc = fmaf(e3.y,w.y,acc); acc = fmaf(e3.z,w.z,acc); acc = fmaf(e3.w,w.w,acc);
    w = wp[q + 16]; acc = fmaf(e4.x,w.x,acc); acc = fmaf(e4.y,w.y,acc); acc = fmaf(e4.z,w.z,acc); acc = fmaf(e4.w,w.w,acc);
    w = wp[q + 20]; acc = fmaf(e5.x,w.x,acc); acc = fmaf(e5.y,w.y,acc); acc = fmaf(e5.z,w.z,acc); acc = fmaf(e5.w,w.w,acc);
    w = wp[q + 24]; acc = fmaf(e6.x,w.x,acc); acc = fmaf(e6.y,w.y,acc); acc = fmaf(e6.z,w.z,acc); acc = fmaf(e6.w,w.w,acc);
    w = wp[q + 28]; acc = fmaf(e7.x,w.x,acc); acc = fmaf(e7.y,w.y,acc); acc = fmaf(e7.z,w.z,acc); acc = fmaf(e7.w,w.w,acc);

    // reduce across the 4 lanes sharing this row
    acc += __shfl_xor_sync(0xffffffffu, acc, 1);
    acc += __shfl_xor_sync(0xffffffffu, acc, 2);
    if (valid && q == 0) g_proj[row] = acc;
}

// Kernel 2: 1024 blocks x 128 threads; block (b,h) pools tokens [h*512, h*512+512).
// Finalize is FOLDED IN: each block writes its partial, fences, takes a ticket;
// the 4th arriver for row b combines the partials, writes out[b], and resets
// the ticket to 0 (device globals start 0; reset keeps graph replays correct).
__global__ void __launch_bounds__(128) pool_kernel(const int* __restrict__ text,
                                                   const int* __restrict__ lengths,
                                                   const float* __restrict__ fc_b,
                                                   float* __restrict__ out) {
    __shared__ float sred[4];
    const int bid = blockIdx.x;
    const int b   = bid >> 2;
    const int h   = bid & 3;
    const int tid = threadIdx.x;
    const int len = lengths[b];

    const int base = h * 512;
    int4 t = reinterpret_cast<const int4*>(text + (size_t)b * S + base)[tid];
    const int s = base + tid * 4;
    float acc = 0.0f;
    if (s + 0 < len) acc += g_proj[t.x];
    if (s + 1 < len) acc += g_proj[t.y];
    if (s + 2 < len) acc += g_proj[t.z];
    if (s + 3 < len) acc += g_proj[t.w];

    #pragma unroll
    for (int off = 16; off; off >>= 1)
        acc += __shfl_xor_sync(0xffffffffu, acc, off);
    const int lane = tid & 31, warp = tid >> 5;
    if (lane == 0) sred[warp] = acc;
    __syncthreads();

    if (tid == 0) {
        g_part[bid] = sred[0] + sred[1] + sred[2] + sred[3];
        __threadfence();                       // partial visible before ticket
        unsigned int old = atomicAdd(&g_cnt[b], 1u);
        if (old == 3u) {                       // last arriver for row b
            __threadfence();
            float v = __ldcg(&g_part[b * 4 + 0]) + __ldcg(&g_part[b * 4 + 1])
                    + __ldcg(&g_part[b * 4 + 2]) + __ldcg(&g_part[b * 4 + 3]);
            out[b] = v / (float)len + fc_b[0];
            g_cnt[b] = 0u;                     // re-arm for next graph replay
        }
    }
}

extern "C" void kernel_launch(void* const* d_in, const int* in_sizes, int n_in,
                              void* d_out, int out_size) {
    const int*   text    = (const int*)d_in[0];
    const int*   lengths = (const int*)d_in[1];
    const float* emb     = (const float*)d_in[2];
    const float* fc_w    = (const float*)d_in[3];
    const float* fc_b    = (const float*)d_in[4];
    float* out = (float*)d_out;

    proj_kernel<<<(V + 63) / 64, 256>>>(emb, fc_w);
    pool_kernel<<<B * 4, 128>>>(text, lengths, fc_b, out);
}

// round 6
// speedup vs baseline: 1.1373x; 1.1373x over previous
#include <cuda_runtime.h>

#define B 256
#define S 2048
#define V 100000
#define E 128

// __device__ scratch (no cudaMalloc allowed).
__device__ float g_proj[V];   // proj[v] = dot(emb[v], fc_w)

// Kernel 1 v4: full-line layout. Warp handles 8 rows (4 KB contiguous).
// Lane = (r = lane>>3, c = lane&7): 8 lanes x 16B = one full 128B line.
// Load k (k=0..7): 4 rows (r) x line (k&3) of row group (k>>2)*4 — every
// LDG.128 moves 4 complete cache lines (1 wavefront per line, full-line DRAM
// requests). All 8 loads issued before any use (MLP=8/lane).
// Reduction: rows sit on disjoint 8-lane groups -> 3 butterfly shuffles
// reduce 4 rows simultaneously; 6 shuffles total per 8 rows.
__global__ void __launch_bounds__(256, 3) proj_kernel(const float* __restrict__ emb,
                                                      const float* __restrict__ fc_w) {
    const int lane = threadIdx.x & 31;
    const int warp = threadIdx.x >> 5;
    const int c = lane & 7;        // column chunk: float4 within a 128B line? no: c*16B within line
    const int r = lane >> 3;       // row within quad (0..3)

    const int gbase = blockIdx.x * 64 + warp * 8;   // first of 8 rows

    // rows for the two quads (clamped so all lanes stay converged)
    const int rowA = min(gbase + r,     V - 1);
    const int rowB = min(gbase + 4 + r, V - 1);

    const float4* e4 = reinterpret_cast<const float4*>(emb);
    // float4 index of (row, line j, chunk c) = row*32 + j*8 + c
    const size_t baseA = (size_t)rowA * 32 + c;
    const size_t baseB = (size_t)rowB * 32 + c;

    // --- 8 independent full-line loads, front-batched ---
    float4 a0 = e4[baseA +  0];
    float4 a1 = e4[baseA +  8];
    float4 a2 = e4[baseA + 16];
    float4 a3 = e4[baseA + 24];
    float4 b0 = e4[baseB +  0];
    float4 b1 = e4[baseB +  8];
    float4 b2 = e4[baseB + 16];
    float4 b3 = e4[baseB + 24];

    // fc_w chunks this lane needs: wp[j*8 + c], j=0..3 (512B table, L1-hot)
    const float4* wp = reinterpret_cast<const float4*>(fc_w);
    const float4 w0 = wp[c +  0];
    const float4 w1 = wp[c +  8];
    const float4 w2 = wp[c + 16];
    const float4 w3 = wp[c + 24];

    float sa = 0.0f, sb = 0.0f;
    sa = fmaf(a0.x,w0.x,sa); sa = fmaf(a0.y,w0.y,sa); sa = fmaf(a0.z,w0.z,sa); sa = fmaf(a0.w,w0.w,sa);
    sa = fmaf(a1.x,w1.x,sa); sa = fmaf(a1.y,w1.y,sa); sa = fmaf(a1.z,w1.z,sa); sa = fmaf(a1.w,w1.w,sa);
    sa = fmaf(a2.x,w2.x,sa); sa = fmaf(a2.y,w2.y,sa); sa = fmaf(a2.z,w2.z,sa); sa = fmaf(a2.w,w2.w,sa);
    sa = fmaf(a3.x,w3.x,sa); sa = fmaf(a3.y,w3.y,sa); sa = fmaf(a3.z,w3.z,sa); sa = fmaf(a3.w,w3.w,sa);
    sb = fmaf(b0.x,w0.x,sb); sb = fmaf(b0.y,w0.y,sb); sb = fmaf(b0.z,w0.z,sb); sb = fmaf(b0.w,w0.w,sb);
    sb = fmaf(b1.x,w1.x,sb); sb = fmaf(b1.y,w1.y,sb); sb = fmaf(b1.z,w1.z,sb); sb = fmaf(b1.w,w1.w,sb);
    sb = fmaf(b2.x,w2.x,sb); sb = fmaf(b2.y,w2.y,sb); sb = fmaf(b2.z,w2.z,sb); sb = fmaf(b2.w,w2.w,sb);
    sb = fmaf(b3.x,w3.x,sb); sb = fmaf(b3.y,w3.y,sb); sb = fmaf(b3.z,w3.z,sb); sb = fmaf(b3.w,w3.w,sb);

    // reduce across the 8 c-lanes (reduces 4 rows per value simultaneously)
    sa += __shfl_xor_sync(0xffffffffu, sa, 1);
    sa += __shfl_xor_sync(0xffffffffu, sa, 2);
    sa += __shfl_xor_sync(0xffffffffu, sa, 4);
    sb += __shfl_xor_sync(0xffffffffu, sb, 1);
    sb += __shfl_xor_sync(0xffffffffu, sb, 2);
    sb += __shfl_xor_sync(0xffffffffu, sb, 4);

    if (c == 0) {
        if (gbase + r     < V) g_proj[gbase + r]     = sa;
        if (gbase + 4 + r < V) g_proj[gbase + 4 + r] = sb;
    }
}

// Kernel 2 v4: one block (256 thr) per batch row; each thread owns 8 tokens.
// Two int4 text loads + up to 8 independent gathers all in flight (MLP=8),
// single block reduction straight to out[b].
__global__ void __launch_bounds__(256) pool_kernel(const int* __restrict__ text,
                                                   const int* __restrict__ lengths,
                                                   const float* __restrict__ fc_b,
                                                   float* __restrict__ out) {
    __shared__ float sred[8];
    const int b = blockIdx.x;
    const int tid = threadIdx.x;
    const int len = lengths[b];

    const int4* row = reinterpret_cast<const int4*>(text + (size_t)b * S);
    int4 t0 = row[tid * 2 + 0];
    int4 t1 = row[tid * 2 + 1];
    const int s = tid * 8;

    float acc = 0.0f;
    if (s + 0 < len) acc += g_proj[t0.x];
    if (s + 1 < len) acc += g_proj[t0.y];
    if (s + 2 < len) acc += g_proj[t0.z];
    if (s + 3 < len) acc += g_proj[t0.w];
    if (s + 4 < len) acc += g_proj[t1.x];
    if (s + 5 < len) acc += g_proj[t1.y];
    if (s + 6 < len) acc += g_proj[t1.z];
    if (s + 7 < len) acc += g_proj[t1.w];

    #pragma unroll
    for (int off = 16; off; off >>= 1)
        acc += __shfl_xor_sync(0xffffffffu, acc, off);
    const int lane = tid & 31, warp = tid >> 5;
    if (lane == 0) sred[warp] = acc;
    __syncthreads();
    if (warp == 0) {
        float v = (lane < 8) ? sred[lane] : 0.0f;
        #pragma unroll
        for (int off = 4; off; off >>= 1)
            v += __shfl_xor_sync(0xffffffffu, v, off);
        if (lane == 0)
            out[b] = v / (float)len + fc_b[0];
    }
}

extern "C" void kernel_launch(void* const* d_in, const int* in_sizes, int n_in,
                              void* d_out, int out_size) {
    const int*   text    = (const int*)d_in[0];
    const int*   lengths = (const int*)d_in[1];
    const float* emb     = (const float*)d_in[2];
    const float* fc_w    = (const float*)d_in[3];
    const float* fc_b    = (const float*)d_in[4];
    float* out = (float*)d_out;

    proj_kernel<<<(V + 63) / 64, 256>>>(emb, fc_w);
    pool_kernel<<<B, 256>>>(text, lengths, fc_b, out);
}

// round 7
// speedup vs baseline: 1.1400x; 1.0025x over previous
#include <cuda_runtime.h>

#define B 256
#define S 2048
#define V 100000
#define E 128

#define PBLK 296                 // 2 resident blocks per SM (148 SMs)
#define NWARPS (PBLK * 8)        // 2368 persistent warps
#define NGROUPS (V / 16)         // 6250 groups of 16 rows (exact: V % 16 == 0)

// __device__ scratch (no cudaMalloc allowed).
__device__ float g_proj[V];   // proj[v] = dot(emb[v], fc_w)

// Kernel 1 v5: persistent grid-stride streaming. Each warp iterates over
// 16-row groups (8 KB contiguous); per iteration it front-batches 16
// independent LDG.128s, each covering one full 128B line (lane c = 16B chunk,
// lane r = row-in-quad). 16 warps/SM x 16 x 128B = 32 KB in flight per SM —
// continuous DRAM pressure, no wave-transition gaps (vs 1563 one-shot blocks).
// fc_w re-read per lane from L1 (512B, always hot). V % 16 == 0: no edge code.
__global__ void __launch_bounds__(256, 2) proj_kernel(const float* __restrict__ emb,
                                                      const float* __restrict__ fc_w) {
    const int lane = threadIdx.x & 31;
    const int warp = threadIdx.x >> 5;
    const int c = lane & 7;        // 16B chunk within the 128B line
    const int r = lane >> 3;       // row within quad (0..3)
    const int gw = blockIdx.x * 8 + warp;

    const float4* e4 = reinterpret_cast<const float4*>(emb);
    const float4* wp = reinterpret_cast<const float4*>(fc_w);
    const float4 w0 = wp[c +  0];
    const float4 w1 = wp[c +  8];
    const float4 w2 = wp[c + 16];
    const float4 w3 = wp[c + 24];

    for (int g = gw; g < NGROUPS; g += NWARPS) {
        const int base = g * 16;                       // first of 16 rows
        // float4 index of (row, line j, chunk c) = row*32 + j*8 + c
        const size_t iA = (size_t)(base      + r) * 32 + c;   // quad 0
        const size_t iB = (size_t)(base + 4  + r) * 32 + c;   // quad 1
        const size_t iC = (size_t)(base + 8  + r) * 32 + c;   // quad 2
        const size_t iD = (size_t)(base + 12 + r) * 32 + c;   // quad 3

        // --- 16 independent full-line loads, front-batched ---
        float4 a0 = e4[iA +  0], a1 = e4[iA +  8], a2 = e4[iA + 16], a3 = e4[iA + 24];
        float4 b0 = e4[iB +  0], b1 = e4[iB +  8], b2 = e4[iB + 16], b3 = e4[iB + 24];
        float4 c0 = e4[iC +  0], c1 = e4[iC +  8], c2 = e4[iC + 16], c3 = e4[iC + 24];
        float4 d0 = e4[iD +  0], d1 = e4[iD +  8], d2 = e4[iD + 16], d3 = e4[iD + 24];

        float sa = 0.f, sb = 0.f, sc = 0.f, sd = 0.f;
        sa = fmaf(a0.x,w0.x,sa); sa = fmaf(a0.y,w0.y,sa); sa = fmaf(a0.z,w0.z,sa); sa = fmaf(a0.w,w0.w,sa);
        sa = fmaf(a1.x,w1.x,sa); sa = fmaf(a1.y,w1.y,sa); sa = fmaf(a1.z,w1.z,sa); sa = fmaf(a1.w,w1.w,sa);
        sa = fmaf(a2.x,w2.x,sa); sa = fmaf(a2.y,w2.y,sa); sa = fmaf(a2.z,w2.z,sa); sa = fmaf(a2.w,w2.w,sa);
        sa = fmaf(a3.x,w3.x,sa); sa = fmaf(a3.y,w3.y,sa); sa = fmaf(a3.z,w3.z,sa); sa = fmaf(a3.w,w3.w,sa);
        sb = fmaf(b0.x,w0.x,sb); sb = fmaf(b0.y,w0.y,sb); sb = fmaf(b0.z,w0.z,sb); sb = fmaf(b0.w,w0.w,sb);
        sb = fmaf(b1.x,w1.x,sb); sb = fmaf(b1.y,w1.y,sb); sb = fmaf(b1.z,w1.z,sb); sb = fmaf(b1.w,w1.w,sb);
        sb = fmaf(b2.x,w2.x,sb); sb = fmaf(b2.y,w2.y,sb); sb = fmaf(b2.z,w2.z,sb); sb = fmaf(b2.w,w2.w,sb);
        sb = fmaf(b3.x,w3.x,sb); sb = fmaf(b3.y,w3.y,sb); sb = fmaf(b3.z,w3.z,sb); sb = fmaf(b3.w,w3.w,sb);
        sc = fmaf(c0.x,w0.x,sc); sc = fmaf(c0.y,w0.y,sc); sc = fmaf(c0.z,w0.z,sc); sc = fmaf(c0.w,w0.w,sc);
        sc = fmaf(c1.x,w1.x,sc); sc = fmaf(c1.y,w1.y,sc); sc = fmaf(c1.z,w1.z,sc); sc = fmaf(c1.w,w1.w,sc);
        sc = fmaf(c2.x,w2.x,sc); sc = fmaf(c2.y,w2.y,sc); sc = fmaf(c2.z,w2.z,sc); sc = fmaf(c2.w,w2.w,sc);
        sc = fmaf(c3.x,w3.x,sc); sc = fmaf(c3.y,w3.y,sc); sc = fmaf(c3.z,w3.z,sc); sc = fmaf(c3.w,w3.w,sc);
        sd = fmaf(d0.x,w0.x,sd); sd = fmaf(d0.y,w0.y,sd); sd = fmaf(d0.z,w0.z,sd); sd = fmaf(d0.w,w0.w,sd);
        sd = fmaf(d1.x,w1.x,sd); sd = fmaf(d1.y,w1.y,sd); sd = fmaf(d1.z,w1.z,sd); sd = fmaf(d1.w,w1.w,sd);
        sd = fmaf(d2.x,w2.x,sd); sd = fmaf(d2.y,w2.y,sd); sd = fmaf(d2.z,w2.z,sd); sd = fmaf(d2.w,w2.w,sd);
        sd = fmaf(d3.x,w3.x,sd); sd = fmaf(d3.y,w3.y,sd); sd = fmaf(d3.z,w3.z,sd); sd = fmaf(d3.w,w3.w,sd);

        // reduce across the 8 c-lanes (all 4 quads simultaneously)
        sa += __shfl_xor_sync(0xffffffffu, sa, 1); sb += __shfl_xor_sync(0xffffffffu, sb, 1);
        sc += __shfl_xor_sync(0xffffffffu, sc, 1); sd += __shfl_xor_sync(0xffffffffu, sd, 1);
        sa += __shfl_xor_sync(0xffffffffu, sa, 2); sb += __shfl_xor_sync(0xffffffffu, sb, 2);
        sc += __shfl_xor_sync(0xffffffffu, sc, 2); sd += __shfl_xor_sync(0xffffffffu, sd, 2);
        sa += __shfl_xor_sync(0xffffffffu, sa, 4); sb += __shfl_xor_sync(0xffffffffu, sb, 4);
        sc += __shfl_xor_sync(0xffffffffu, sc, 4); sd += __shfl_xor_sync(0xffffffffu, sd, 4);

        if (c == 0) {
            g_proj[base      + r] = sa;
            g_proj[base + 4  + r] = sb;
            g_proj[base + 8  + r] = sc;
            g_proj[base + 12 + r] = sd;
        }
    }
}

// Kernel 2: one block (256 thr) per batch row; each thread owns 8 tokens.
// Two int4 text loads + up to 8 independent gathers in flight, single block
// reduction straight to out[b].
__global__ void __launch_bounds__(256) pool_kernel(const int* __restrict__ text,
                                                   const int* __restrict__ lengths,
                                                   const float* __restrict__ fc_b,
                                                   float* __restrict__ out) {
    __shared__ float sred[8];
    const int b = blockIdx.x;
    const int tid = threadIdx.x;
    const int len = lengths[b];

    const int4* row = reinterpret_cast<const int4*>(text + (size_t)b * S);
    int4 t0 = row[tid * 2 + 0];
    int4 t1 = row[tid * 2 + 1];
    const int s = tid * 8;

    float acc = 0.0f;
    if (s + 0 < len) acc += g_proj[t0.x];
    if (s + 1 < len) acc += g_proj[t0.y];
    if (s + 2 < len) acc += g_proj[t0.z];
    if (s + 3 < len) acc += g_proj[t0.w];
    if (s + 4 < len) acc += g_proj[t1.x];
    if (s + 5 < len) acc += g_proj[t1.y];
    if (s + 6 < len) acc += g_proj[t1.z];
    if (s + 7 < len) acc += g_proj[t1.w];

    #pragma unroll
    for (int off = 16; off; off >>= 1)
        acc += __shfl_xor_sync(0xffffffffu, acc, off);
    const int lane = tid & 31, warp = tid >> 5;
    if (lane == 0) sred[warp] = acc;
    __syncthreads();
    if (warp == 0) {
        float v = (lane < 8) ? sred[lane] : 0.0f;
        #pragma unroll
        for (int off = 4; off; off >>= 1)
            v += __shfl_xor_sync(0xffffffffu, v, off);
        if (lane == 0)
            out[b] = v / (float)len + fc_b[0];
    }
}

extern "C" void kernel_launch(void* const* d_in, const int* in_sizes, int n_in,
                              void* d_out, int out_size) {
    const int*   text    = (const int*)d_in[0];
    const int*   lengths = (const int*)d_in[1];
    const float* emb     = (const float*)d_in[2];
    const float* fc_w    = (const float*)d_in[3];
    const float* fc_b    = (const float*)d_in[4];
    float* out = (float*)d_out;

    proj_kernel<<<PBLK, 256>>>(emb, fc_w);
    pool_kernel<<<B, 256>>>(text, lengths, fc_b, out);
}